// round 2
// baseline (speedup 1.0000x reference)
#include <cuda_runtime.h>
#include <cstdint>

// Problem constants (fixed by setup_inputs)
#define T_FRAMES   4096
#define E_FRAME    12288          // 4096 atoms * 3
#define TD_MAXX    512
#define NBLK       63            // frame blocks of 64: t in [0,4031]
#define EC         128           // elements per chunk
#define NCHUNK     (E_FRAME/EC)  // 96
#define CPB        8             // CTAs per frame-block (element split)
#define CPC        (NCHUNK/CPB)  // 12 chunks per CTA
#define XPITCH     132           // 128+4 pad -> conflict-free lane-strided LDS.128
#define NTHR       256
#define NCTA       (NBLK*CPB)    // 504

// floats per pipeline stage: 64 frame rows + 8 origin rows
#define STAGE      (64*XPITCH + 8*EC)      // 9472 floats
#define SMEM_BYTES (2*STAGE*4)             // 75776 B dynamic smem

// Per-CTA partials (fully overwritten every replay -> deterministic, no init kernel)
__device__ float Spart[NCTA * 64];         // [b][f]   : sum_e x[64k+f,e]^2 (chunk-partial)
__device__ float Dpart[NCTA * 512];        // [b][f][o]: dot(x[64k+f], x[64*(o_lo+o)])

__device__ __forceinline__ void cp16(uint32_t dst, const void* src) {
    asm volatile("cp.async.cg.shared.global [%0], [%1], 16;" :: "r"(dst), "l"(src));
}
__device__ __forceinline__ unsigned long long fma2(unsigned long long a,
                                                   unsigned long long b,
                                                   unsigned long long c) {
    unsigned long long d;
    asm("fma.rn.f32x2 %0, %1, %2, %3;" : "=l"(d) : "l"(a), "l"(b), "l"(c));
    return d;
}
__device__ __forceinline__ float hsum2(unsigned long long v) {
    float lo = __uint_as_float((uint32_t)v);
    float hi = __uint_as_float((uint32_t)(v >> 32));
    return lo + hi;
}

__global__ void __launch_bounds__(NTHR, 2) msd_main(const float* __restrict__ x) {
    extern __shared__ float sm[];   // [2][STAGE]; epilogue reuses front as red4[4][64][9]

    const int tid = threadIdx.x;
    const int b   = blockIdx.x;
    const int k   = b / CPB;                 // frames 64k..64k+63
    const int g   = b % CPB;                 // element chunk-group
    const int o_lo = (k > 7) ? (k - 7) : 0;
    const int o_hi = (k < 55) ? k : 55;
    const int n_o  = o_hi - o_lo + 1;        // 1..8 valid origins

    const int w    = tid >> 5, lane = tid & 31;
    const int f    = ((w & 1) << 5) | lane;  // frame-in-block owned by this thread
    const int ev0  = (w >> 1) << 3;          // element subrange start (float4 units)

    const uint32_t sm_base = (uint32_t)__cvta_generic_to_shared(sm);

    // zero the never-loaded origin rows in BOTH stages (disjoint from cp.async targets)
    {
        int nz = (8 - n_o) * EC;
        for (int i = tid; i < nz; i += NTHR) {
            sm[0*STAGE + 64*XPITCH + n_o*EC + i] = 0.0f;
            sm[1*STAGE + 64*XPITCH + n_o*EC + i] = 0.0f;
        }
    }

    // issue all loads for one chunk into stage s
    auto load_chunk = [&](int cc, int s) {
        const int cbase = (g * CPC + cc) * EC;
        const uint32_t xs = sm_base + (uint32_t)(s * STAGE) * 4u;
        const uint32_t os = xs + (uint32_t)(64 * XPITCH) * 4u;
        #pragma unroll
        for (int j = 0; j < 8; ++j) {
            int i   = tid + j * NTHR;        // 0..2047
            int row = i >> 5;
            int c16 = i & 31;
            const float* src = x + (size_t)(64 * k + row) * E_FRAME + cbase + (c16 << 2);
            cp16(xs + (uint32_t)(row * XPITCH + (c16 << 2)) * 4u, src);
        }
        int o   = tid >> 5;
        int c16 = tid & 31;
        if (o < n_o) {
            const float* src = x + (size_t)(64 * (o_lo + o)) * E_FRAME + cbase + (c16 << 2);
            cp16(os + (uint32_t)(o * EC + (c16 << 2)) * 4u, src);
        }
    };

    // packed-f32x2 accumulators
    unsigned long long accA[8], accB[8], ssA = 0ull, ssB = 0ull;
    #pragma unroll
    for (int o = 0; o < 8; ++o) { accA[o] = 0ull; accB[o] = 0ull; }

    load_chunk(0, 0);
    asm volatile("cp.async.commit_group;");

    for (int cc = 0; cc < CPC; ++cc) {
        if (cc + 1 < CPC) {
            load_chunk(cc + 1, (cc + 1) & 1);   // buffer was freed by prior trailing sync
            asm volatile("cp.async.commit_group;");
            asm volatile("cp.async.wait_group 1;");
        } else {
            asm volatile("cp.async.wait_group 0;");
        }
        __syncthreads();

        const float* stf = sm + (cc & 1) * STAGE;
        const ulonglong2* xr  = (const ulonglong2*)(stf + f * XPITCH);
        const ulonglong2* orp = (const ulonglong2*)(stf + 64 * XPITCH);
        #pragma unroll
        for (int v = 0; v < 8; ++v) {
            ulonglong2 xv = xr[ev0 + v];
            ssA = fma2(xv.x, xv.x, ssA);
            ssB = fma2(xv.y, xv.y, ssB);
            #pragma unroll
            for (int o = 0; o < 8; ++o) {
                ulonglong2 ov = orp[(o << 5) + ev0 + v];  // uniform addr -> broadcast
                accA[o] = fma2(xv.x, ov.x, accA[o]);
                accB[o] = fma2(xv.y, ov.y, accB[o]);
            }
        }
        __syncthreads();   // stage consumed; safe to refill next iteration
    }

    // ---- epilogue: reduce 4 element-subrange groups, write partials ----
    float* red4 = sm;                   // reuse stage memory: [4][64][9]
    {
        float* my = red4 + (w >> 1) * 576 + f * 9;
        my[8] = hsum2(ssA) + hsum2(ssB);
        #pragma unroll
        for (int o = 0; o < 8; ++o) my[o] = hsum2(accA[o]) + hsum2(accB[o]);
    }
    __syncthreads();

    for (int p = tid; p < 512; p += NTHR) {
        int ff = p >> 3, o = p & 7;
        int idx = ff * 9 + o;
        Dpart[(size_t)b * 512 + p] =
            red4[idx] + red4[576 + idx] + red4[1152 + idx] + red4[1728 + idx];
    }
    if (tid < 64) {
        int idx = tid * 9 + 8;
        Spart[b * 64 + tid] =
            red4[idx] + red4[576 + idx] + red4[1152 + idx] + red4[1728 + idx];
    }
}

// Gather partials into msd[td]. td = 64*D + ff; origin j, frame block k = j+D.
__global__ void msd_fin(float* __restrict__ out) {
    __shared__ float partS0[64];
    __shared__ float sS0;
    const int tid = threadIdx.x;                 // 64 threads
    // S0 = sum_j sum_g Spart[(j*8+g)][0]
    float a = 0.0f;
    for (int i = tid; i < 56 * 8; i += 64) a += Spart[i * 64 + 0];
    partS0[tid] = a;
    __syncthreads();
    if (tid == 0) {
        float s = 0.0f;
        #pragma unroll
        for (int i = 0; i < 64; ++i) s += partS0[i];
        sS0 = s;
    }
    __syncthreads();

    const int td = blockIdx.x * 64 + tid;
    const int D  = td >> 6, ff = td & 63;
    float r = sS0;
    for (int j = 0; j < 56; ++j) {
        int k = j + D;
        int o = (k <= 7) ? j : (7 - D);          // j - max(0, k-7)
        float s = 0.0f, d = 0.0f;
        #pragma unroll
        for (int g = 0; g < 8; ++g) {
            int bb = k * 8 + g;
            s += Spart[bb * 64 + ff];
            d += Dpart[(size_t)bb * 512 + ff * 8 + o];
        }
        r += s - 2.0f * d;
    }
    out[td] = r * (1.0f / (56.0f * 12288.0f));
}

extern "C" void kernel_launch(void* const* d_in, const int* in_sizes, int n_in,
                              void* d_out, int out_size) {
    const float* x = (const float*)d_in[0];
    float* out = (float*)d_out;
    cudaFuncSetAttribute(msd_main, cudaFuncAttributeMaxDynamicSharedMemorySize, SMEM_BYTES);
    msd_main<<<NCTA, NTHR, SMEM_BYTES>>>(x);
    msd_fin<<<TD_MAXX / 64, 64>>>(out);
}

// round 3
// speedup vs baseline: 1.4682x; 1.4682x over previous
#include <cuda_runtime.h>
#include <cstdint>

// Problem constants (fixed by setup_inputs)
#define T_FRAMES   4096
#define E_FRAME    12288          // 4096 atoms * 3
#define TD_MAXX    512
#define NBLK       63            // frame blocks of 64: t in [0,4031]
#define EC         128           // elements per chunk
#define NCHUNK     (E_FRAME/EC)  // 96
#define CPB        8             // CTAs per frame-block (element split)
#define CPC        (NCHUNK/CPB)  // 12 chunks per CTA
#define XPITCH     132           // 128+4 pad -> conflict-free lane-strided LDS.128
#define NTHR       256
#define NCTA       (NBLK*CPB)    // 504

// floats per pipeline stage: 64 frame rows + 8 origin rows
#define STAGE      (64*XPITCH + 8*EC)      // 9472 floats
#define SMEM_BYTES (2*STAGE*4)             // 75776 B dynamic smem

// Per-CTA partials (fully overwritten every replay -> deterministic, no init kernel)
__device__ float Spart[NCTA * 64];         // [b][f]   : sum_e x[64k+f,e]^2 (chunk-partial)
__device__ float Dpart[NCTA * 512];        // [b][f][o]: dot(x[64k+f], x[64*(o_lo+o)])

__device__ __forceinline__ void cp16(uint32_t dst, const void* src) {
    asm volatile("cp.async.cg.shared.global [%0], [%1], 16;" :: "r"(dst), "l"(src));
}
__device__ __forceinline__ unsigned long long fma2(unsigned long long a,
                                                   unsigned long long b,
                                                   unsigned long long c) {
    unsigned long long d;
    asm("fma.rn.f32x2 %0, %1, %2, %3;" : "=l"(d) : "l"(a), "l"(b), "l"(c));
    return d;
}
__device__ __forceinline__ float hsum2(unsigned long long v) {
    float lo = __uint_as_float((uint32_t)v);
    float hi = __uint_as_float((uint32_t)(v >> 32));
    return lo + hi;
}

__global__ void __launch_bounds__(NTHR, 2) msd_main(const float* __restrict__ x) {
    extern __shared__ float sm[];   // [2][STAGE]; epilogue reuses front as red4[4][64][9]

    const int tid = threadIdx.x;
    const int b   = blockIdx.x;
    const int k   = b / CPB;                 // frames 64k..64k+63
    const int g   = b % CPB;                 // element chunk-group
    const int o_lo = (k > 7) ? (k - 7) : 0;
    const int o_hi = (k < 55) ? k : 55;
    const int n_o  = o_hi - o_lo + 1;        // 1..8 valid origins

    const int w    = tid >> 5, lane = tid & 31;
    const int f    = ((w & 1) << 5) | lane;  // frame-in-block owned by this thread
    const int ev0  = (w >> 1) << 3;          // element subrange start (float4 units)

    const uint32_t sm_base = (uint32_t)__cvta_generic_to_shared(sm);

    // zero the never-loaded origin rows in BOTH stages (disjoint from cp.async targets)
    {
        int nz = (8 - n_o) * EC;
        for (int i = tid; i < nz; i += NTHR) {
            sm[0*STAGE + 64*XPITCH + n_o*EC + i] = 0.0f;
            sm[1*STAGE + 64*XPITCH + n_o*EC + i] = 0.0f;
        }
    }

    // issue all loads for one chunk into stage s
    auto load_chunk = [&](int cc, int s) {
        const int cbase = (g * CPC + cc) * EC;
        const uint32_t xs = sm_base + (uint32_t)(s * STAGE) * 4u;
        const uint32_t os = xs + (uint32_t)(64 * XPITCH) * 4u;
        #pragma unroll
        for (int j = 0; j < 8; ++j) {
            int i   = tid + j * NTHR;        // 0..2047
            int row = i >> 5;
            int c16 = i & 31;
            const float* src = x + (size_t)(64 * k + row) * E_FRAME + cbase + (c16 << 2);
            cp16(xs + (uint32_t)(row * XPITCH + (c16 << 2)) * 4u, src);
        }
        int o   = tid >> 5;
        int c16 = tid & 31;
        if (o < n_o) {
            const float* src = x + (size_t)(64 * (o_lo + o)) * E_FRAME + cbase + (c16 << 2);
            cp16(os + (uint32_t)(o * EC + (c16 << 2)) * 4u, src);
        }
    };

    // packed-f32x2 accumulators
    unsigned long long accA[8], accB[8], ssA = 0ull, ssB = 0ull;
    #pragma unroll
    for (int o = 0; o < 8; ++o) { accA[o] = 0ull; accB[o] = 0ull; }

    load_chunk(0, 0);
    asm volatile("cp.async.commit_group;");

    for (int cc = 0; cc < CPC; ++cc) {
        if (cc + 1 < CPC) {
            load_chunk(cc + 1, (cc + 1) & 1);   // buffer was freed by prior trailing sync
            asm volatile("cp.async.commit_group;");
            asm volatile("cp.async.wait_group 1;");
        } else {
            asm volatile("cp.async.wait_group 0;");
        }
        __syncthreads();

        const float* stf = sm + (cc & 1) * STAGE;
        const ulonglong2* xr  = (const ulonglong2*)(stf + f * XPITCH);
        const ulonglong2* orp = (const ulonglong2*)(stf + 64 * XPITCH);
        #pragma unroll
        for (int v = 0; v < 8; ++v) {
            ulonglong2 xv = xr[ev0 + v];
            ssA = fma2(xv.x, xv.x, ssA);
            ssB = fma2(xv.y, xv.y, ssB);
            #pragma unroll
            for (int o = 0; o < 8; ++o) {
                ulonglong2 ov = orp[(o << 5) + ev0 + v];  // uniform addr -> broadcast
                accA[o] = fma2(xv.x, ov.x, accA[o]);
                accB[o] = fma2(xv.y, ov.y, accB[o]);
            }
        }
        __syncthreads();   // stage consumed; safe to refill next iteration
    }

    // ---- epilogue: reduce 4 element-subrange groups, write partials ----
    float* red4 = sm;                   // reuse stage memory: [4][64][9]
    {
        float* my = red4 + (w >> 1) * 576 + f * 9;
        my[8] = hsum2(ssA) + hsum2(ssB);
        #pragma unroll
        for (int o = 0; o < 8; ++o) my[o] = hsum2(accA[o]) + hsum2(accB[o]);
    }
    __syncthreads();

    for (int p = tid; p < 512; p += NTHR) {
        int ff = p >> 3, o = p & 7;
        int idx = ff * 9 + o;
        Dpart[(size_t)b * 512 + p] =
            red4[idx] + red4[576 + idx] + red4[1152 + idx] + red4[1728 + idx];
    }
    if (tid < 64) {
        int idx = tid * 9 + 8;
        Spart[b * 64 + tid] =
            red4[idx] + red4[576 + idx] + red4[1152 + idx] + red4[1728 + idx];
    }
}

// Parallel gather: one CTA per td, 256 threads reduce the 448 (j,g) pairs.
// msd_sum[td] = sum_j { S[t0_j] + S[t0_j+td] - 2*dot } ; k = j + (td>>6), ff = td&63.
__global__ void __launch_bounds__(256) msd_fin(float* __restrict__ out) {
    __shared__ float red[256];
    const int td  = blockIdx.x;
    const int D   = td >> 6, ff = td & 63;
    const int tid = threadIdx.x;

    float acc = 0.0f;
    #pragma unroll 2
    for (int p = tid; p < 56 * 8; p += 256) {
        int j = p >> 3, g = p & 7;
        int k = j + D;
        int o = (k <= 7) ? j : (7 - D);          // j - max(0, k-7)
        int bb = k * 8 + g;
        int jb = j * 8 + g;
        acc += Spart[jb * 64]                        // S[t0_j]   (frame 64j, g-chunk)
             + Spart[bb * 64 + ff]                   // S[t0_j+td]
             - 2.0f * Dpart[(size_t)bb * 512 + ff * 8 + o];
    }
    red[tid] = acc;
    __syncthreads();
    #pragma unroll
    for (int s = 128; s > 0; s >>= 1) {
        if (tid < s) red[tid] += red[tid + s];
        __syncthreads();
    }
    if (tid == 0) out[td] = red[0] * (1.0f / (56.0f * 12288.0f));
}

extern "C" void kernel_launch(void* const* d_in, const int* in_sizes, int n_in,
                              void* d_out, int out_size) {
    const float* x = (const float*)d_in[0];
    float* out = (float*)d_out;
    cudaFuncSetAttribute(msd_main, cudaFuncAttributeMaxDynamicSharedMemorySize, SMEM_BYTES);
    msd_main<<<NCTA, NTHR, SMEM_BYTES>>>(x);
    msd_fin<<<TD_MAXX, 256>>>(out);
}